// round 4
// baseline (speedup 1.0000x reference)
#include <cuda_runtime.h>
#include <math_constants.h>
#include <float.h>

// Problem constants (fixed by setup_inputs): B=64, Nt=64, Ns=4096, C=256,
// WIN=2, TOPK=3, GH=GW=4, 16 gabor kernels.
#define BMAX 64

__device__ float g_winsum[BMAX * 1024];

__device__ __forceinline__ float4 max4(float4 a, float4 b) {
    return make_float4(fmaxf(a.x, b.x), fmaxf(a.y, b.y),
                       fmaxf(a.z, b.z), fmaxf(a.w, b.w));
}

// ---------------------------------------------------------------------------
// Kernel 1 (fused): each block computes zmax[b] from z (redundantly across the
// 32 blocks of a batch — z is 4MB total so the replays are L2 hits), then the
// per-window response sums for its row of 32 windows.
// winsum[b, wh*32+ww] = sum_{i,j} dot(x[b, (2wh+i)*64 + 2ww+j, :], zmax[b,:])
// 8 warps; each warp owns 4 windows with independent accumulators; loads
// front-batched per row-pair for MLP; shuffle-reduce at the end.
// ---------------------------------------------------------------------------
__global__ void __launch_bounds__(256) k_winsum(const float* __restrict__ x,
                                                const float* __restrict__ z) {
    int b  = blockIdx.x >> 5;
    int wh = blockIdx.x & 31;
    __shared__ float4 szg[4][64];
    __shared__ float4 sz[64];
    int tid = threadIdx.x;

    // --- zmax[b] into sz: 4 token-groups x 64 float4 channel-lanes ---
    {
        int g  = tid >> 6;       // token group 0..3 (16 tokens each)
        int c4 = tid & 63;       // float4 channel lane
        const float4* zp = (const float4*)(z + ((size_t)b * 64 + g * 16) * 256) + c4;
        float4 m = make_float4(-FLT_MAX, -FLT_MAX, -FLT_MAX, -FLT_MAX);
#pragma unroll
        for (int t = 0; t < 16; ++t) m = max4(m, zp[t * 64]);
        szg[g][c4] = m;
    }
    __syncthreads();
    if (tid < 64)
        sz[tid] = max4(max4(szg[0][tid], szg[1][tid]),
                       max4(szg[2][tid], szg[3][tid]));
    __syncthreads();

    int warp = tid >> 5, lane = tid & 31;
    const float* xb = x + (size_t)b * 4096 * 256 + (size_t)wh * 128 * 256
                        + (size_t)warp * 4 * 2 * 256;

    float acc[4] = {0.f, 0.f, 0.f, 0.f};
#pragma unroll
    for (int r = 0; r < 4; ++r) {
        int off = ((r >> 1) * 64 + (r & 1)) * 256;   // rows s, s+1, s+64, s+65
        float4 va[4], vb[4];
#pragma unroll
        for (int q = 0; q < 4; ++q) {                // batch 8 loads before FMAs
            const float4* p4 = (const float4*)(xb + q * 512 + off);
            va[q] = p4[lane];
            vb[q] = p4[lane + 32];
        }
        float4 za = sz[lane], zb = sz[lane + 32];
#pragma unroll
        for (int q = 0; q < 4; ++q) {
            acc[q] += va[q].x * za.x + va[q].y * za.y + va[q].z * za.z + va[q].w * za.w;
            acc[q] += vb[q].x * zb.x + vb[q].y * zb.y + vb[q].z * zb.z + vb[q].w * zb.w;
        }
    }
#pragma unroll
    for (int q = 0; q < 4; ++q) {
        float a = acc[q];
#pragma unroll
        for (int o = 16; o > 0; o >>= 1) a += __shfl_down_sync(0xffffffffu, a, o);
        if (lane == 0) g_winsum[b * 1024 + wh * 32 + warp * 4 + q] = a;
    }
}

// ---------------------------------------------------------------------------
// Kernel 2 (fused tail): per-batch gabor map (16 cells x 16 kernels, one term
// per thread, width-16 shuffle reduce), top-3 window select (descending,
// ties -> lowest index, matching jax.lax.top_k), then gather + bilinear 2->4
// upsample + (1+gmap) scale + write. One block per batch, thread per channel.
// jax half-pixel bilinear 2->4 weights: {1,0},{.75,.25},{.25,.75},{0,1}.
// ---------------------------------------------------------------------------
__global__ void __launch_bounds__(256) k_tail(
        const float* __restrict__ x, float* __restrict__ out,
        const float* __restrict__ gth, const float* __restrict__ gsg,
        const float* __restrict__ glm, const float* __restrict__ gps,
        const float* __restrict__ ggm, const float* __restrict__ gwt) {
    int b = blockIdx.x;
    __shared__ float sv[1024];
    __shared__ float rv[256];
    __shared__ int   ri[256];
    __shared__ int   sidx[3];
    __shared__ float s_gmap[16];
    int tid = threadIdx.x;
#pragma unroll
    for (int k = 0; k < 4; ++k) sv[tid + k * 256] = g_winsum[b * 1024 + tid + k * 256];

    // Gabor map: tid = cell*16 + k, one transcendental round per thread.
    {
        int cell = tid >> 4;
        int k    = tid & 15;
        int h = cell >> 2, w = cell & 3;
        float yy = (float)h - 1.5f;
        float xx = (float)w - 1.5f;
        float theta = gth[k] * (2.f * CUDART_PI_F);
        float ct = cosf(theta), st = sinf(theta);
        float xp =  xx * ct + yy * st;
        float yp = -xx * st + yy * ct;
        float sig = gsg[k] + 0.5f;
        float lmb = glm[k] + 0.5f;
        float gam = ggm[k];
        float env = expf(-(xp * xp + gam * gam * yp * yp) / (2.f * sig * sig));
        float car = cosf(2.f * CUDART_PI_F * xp / lmb + gps[k]);
        float term = gwt[k] * env * car;
#pragma unroll
        for (int o = 8; o > 0; o >>= 1)
            term += __shfl_down_sync(0xffffffffu, term, o, 16);
        if (k == 0) s_gmap[cell] = 1.f + term;   // splat + x_up = x_up*(1+gmap)
    }
    __syncthreads();

    for (int r = 0; r < 3; ++r) {
        float bv = -FLT_MAX; int bi = 1 << 30;
#pragma unroll
        for (int k = 0; k < 4; ++k) {
            int i = tid + k * 256;
            float v = sv[i];
            if (v > bv || (v == bv && i < bi)) { bv = v; bi = i; }
        }
        rv[tid] = bv; ri[tid] = bi;
        __syncthreads();
        for (int s = 128; s > 0; s >>= 1) {
            if (tid < s) {
                float ov = rv[tid + s]; int oi = ri[tid + s];
                if (ov > rv[tid] || (ov == rv[tid] && oi < ri[tid])) { rv[tid] = ov; ri[tid] = oi; }
            }
            __syncthreads();
        }
        if (tid == 0) { sidx[r] = ri[0]; sv[ri[0]] = -FLT_MAX; }
        __syncthreads();
    }

    const float wa[4] = {1.f, 0.75f, 0.25f, 0.f};
    const float wb[4] = {0.f, 0.25f, 0.75f, 1.f};
    int c = tid;

#pragma unroll
    for (int t = 0; t < 3; ++t) {
        int widx = sidx[t];
        int wh = widx >> 5, ww = widx & 31;
        const float* p = x + ((size_t)b * 4096 + wh * 128 + ww * 2) * 256 + c;
        float v00 = p[0];          // (i=0,j=0)
        float v01 = p[256];        // (i=0,j=1)
        float v10 = p[64 * 256];   // (i=1,j=0)
        float v11 = p[65 * 256];   // (i=1,j=1)

        float* ob = out + ((size_t)b * 48 + t * 16) * 256 + c;
#pragma unroll
        for (int gh = 0; gh < 4; ++gh) {
            float u0 = wa[gh] * v00 + wb[gh] * v10;  // interp along i (rows)
            float u1 = wa[gh] * v01 + wb[gh] * v11;
#pragma unroll
            for (int gw = 0; gw < 4; ++gw) {
                float val = wa[gw] * u0 + wb[gw] * u1;  // interp along j (cols)
                ob[(gh * 4 + gw) * 256] = val * s_gmap[gh * 4 + gw];
            }
        }
    }
}

// ---------------------------------------------------------------------------
extern "C" void kernel_launch(void* const* d_in, const int* in_sizes, int n_in,
                              void* d_out, int out_size) {
    const float* z   = (const float*)d_in[0];
    const float* x   = (const float*)d_in[1];
    const float* gth = (const float*)d_in[2];
    const float* gsg = (const float*)d_in[3];
    const float* glm = (const float*)d_in[4];
    const float* gps = (const float*)d_in[5];
    const float* ggm = (const float*)d_in[6];
    const float* gwt = (const float*)d_in[7];
    float* out = (float*)d_out;

    int B = in_sizes[0] / (64 * 256);   // z is (B, 64, 256)

    k_winsum<<<B * 32, 256>>>(x, z);
    k_tail  <<<B,      256>>>(x, out, gth, gsg, glm, gps, ggm, gwt);
}

// round 5
// speedup vs baseline: 1.0182x; 1.0182x over previous
#include <cuda_runtime.h>
#include <math_constants.h>
#include <float.h>

// Problem constants (fixed by setup_inputs): B=64, Nt=64, Ns=4096, C=256,
// WIN=2, TOPK=3, GH=GW=4, 16 gabor kernels.
#define BMAX 64

__device__ float g_zmax[BMAX * 256];
__device__ float g_winsum[BMAX * 1024];
__device__ float g_gmap[16];

__device__ __forceinline__ float4 max4(float4 a, float4 b) {
    return make_float4(fmaxf(a.x, b.x), fmaxf(a.y, b.y),
                       fmaxf(a.z, b.z), fmaxf(a.w, b.w));
}

// better(v,i, w,j): strictly greater value, or equal value with lower index
// (matches jax.lax.top_k ordering).
__device__ __forceinline__ bool better(float v, int i, float w, int j) {
    return v > w || (v == w && i < j);
}
__device__ __forceinline__ void insert3(float v, int i, float* rv, int* ri) {
    if (better(v, i, rv[0], ri[0])) {
        rv[2] = rv[1]; ri[2] = ri[1];
        rv[1] = rv[0]; ri[1] = ri[0];
        rv[0] = v;     ri[0] = i;
    } else if (better(v, i, rv[1], ri[1])) {
        rv[2] = rv[1]; ri[2] = ri[1];
        rv[1] = v;     ri[1] = i;
    } else if (better(v, i, rv[2], ri[2])) {
        rv[2] = v;     ri[2] = i;
    }
}

// ---------------------------------------------------------------------------
// Kernel 1: z_max. grid = B*4 + 1. Blocks [0, B*4): batch b = blk/4, channel
// group cg = blk%4 (64 channels). 256 threads = 16 token-groups x 16 float4
// lanes, 4 token-loads each -> high MLP, ~131K threads for the 4MB read.
// Block B*4 computes the 4x4 gabor map fully in parallel (cell x k per thread).
// ---------------------------------------------------------------------------
__global__ void __launch_bounds__(256) k_zmax(
        const float* __restrict__ z, int B,
        const float* __restrict__ gth, const float* __restrict__ gsg,
        const float* __restrict__ glm, const float* __restrict__ gps,
        const float* __restrict__ ggm, const float* __restrict__ gwt) {
    int blk = blockIdx.x;
    int tid = threadIdx.x;

    if (blk == B * 4) {   // gabor block
        int cell = tid >> 4;       // 0..15 -> (h,w)
        int k    = tid & 15;       // gabor kernel index
        int h = cell >> 2, w = cell & 3;
        float yy = (float)h - 1.5f;
        float xx = (float)w - 1.5f;
        float theta = gth[k] * (2.f * CUDART_PI_F);
        float ct = cosf(theta), st = sinf(theta);
        float xp =  xx * ct + yy * st;
        float yp = -xx * st + yy * ct;
        float sig = gsg[k] + 0.5f;
        float lmb = glm[k] + 0.5f;
        float gam = ggm[k];
        float env = expf(-(xp * xp + gam * gam * yp * yp) / (2.f * sig * sig));
        float car = cosf(2.f * CUDART_PI_F * xp / lmb + gps[k]);
        float term = gwt[k] * env * car;
#pragma unroll
        for (int o = 8; o > 0; o >>= 1)
            term += __shfl_down_sync(0xffffffffu, term, o, 16);
        if (k == 0) g_gmap[cell] = 1.f + term;  // splat + x_up = x_up*(1+gmap)
        return;
    }

    int b  = blk >> 2;
    int cg = blk & 3;              // 64-channel group
    int tg = tid >> 4;             // token group (4 tokens each)
    int c4 = tid & 15;             // float4 lane within group
    __shared__ float4 sm[16][16];

    const float4* zp = (const float4*)(z + ((size_t)b * 64 + tg * 4) * 256) + cg * 16 + c4;
    float4 m = zp[0];
    m = max4(m, zp[64]);
    m = max4(m, zp[128]);
    m = max4(m, zp[192]);
    sm[tg][c4] = m;
    __syncthreads();

    if (tid < 16) {
        float4 r = sm[0][tid];
#pragma unroll
        for (int g = 1; g < 16; ++g) r = max4(r, sm[g][tid]);
        ((float4*)(g_zmax + b * 256 + cg * 64))[tid] = r;
    }
}

// ---------------------------------------------------------------------------
// Kernel 2: per-window sum of response over the 4 pixels of each 2x2 window.
// winsum[b, wh*32+ww] = sum_{i,j} dot(x[b, (2wh+i)*64 + 2ww+j, :], zmax[b,:])
// One block per (b, wh). 8 warps; each warp owns 4 windows with independent
// accumulators; loads front-batched per row-pair for MLP; shuffles at end.
// ---------------------------------------------------------------------------
__global__ void __launch_bounds__(256) k_winsum(const float* __restrict__ x) {
    int b  = blockIdx.x >> 5;
    int wh = blockIdx.x & 31;
    __shared__ float4 sz[64];
    int tid = threadIdx.x;
    if (tid < 64) sz[tid] = ((const float4*)(g_zmax + b * 256))[tid];
    __syncthreads();

    int warp = tid >> 5, lane = tid & 31;
    const float* xb = x + (size_t)b * 4096 * 256 + (size_t)wh * 128 * 256
                        + (size_t)warp * 4 * 2 * 256;

    float acc[4] = {0.f, 0.f, 0.f, 0.f};
#pragma unroll
    for (int r = 0; r < 4; ++r) {
        int off = ((r >> 1) * 64 + (r & 1)) * 256;   // rows s, s+1, s+64, s+65
        float4 va[4], vb[4];
#pragma unroll
        for (int q = 0; q < 4; ++q) {                // batch 8 loads before FMAs
            const float4* p4 = (const float4*)(xb + q * 512 + off);
            va[q] = p4[lane];
            vb[q] = p4[lane + 32];
        }
        float4 za = sz[lane], zb = sz[lane + 32];
#pragma unroll
        for (int q = 0; q < 4; ++q) {
            acc[q] += va[q].x * za.x + va[q].y * za.y + va[q].z * za.z + va[q].w * za.w;
            acc[q] += vb[q].x * zb.x + vb[q].y * zb.y + vb[q].z * zb.z + vb[q].w * zb.w;
        }
    }
#pragma unroll
    for (int q = 0; q < 4; ++q) {
        float a = acc[q];
#pragma unroll
        for (int o = 16; o > 0; o >>= 1) a += __shfl_down_sync(0xffffffffu, a, o);
        if (lane == 0) g_winsum[b * 1024 + wh * 32 + warp * 4 + q] = a;
    }
}

// ---------------------------------------------------------------------------
// Kernel 3 (tail): per-batch top-3 via warp-shuffle triple merge (2 barriers
// total), then gather + bilinear 2->4 upsample + (1+gmap) scale + write.
// One block per batch, thread per channel.
// jax half-pixel bilinear 2->4 weights: {1,0},{.75,.25},{.25,.75},{0,1}.
// ---------------------------------------------------------------------------
__global__ void __launch_bounds__(256) k_tail(const float* __restrict__ x,
                                              float* __restrict__ out) {
    int b = blockIdx.x;
    __shared__ float wv[8][3];
    __shared__ int   wi[8][3];
    __shared__ int   sidx[3];
    __shared__ float s_gmap[16];
    int tid = threadIdx.x;
    int warp = tid >> 5, lane = tid & 31;

    if (tid < 16) s_gmap[tid] = g_gmap[tid];

    // Local top-3 over this thread's 4 values.
    float rv[3] = {-FLT_MAX, -FLT_MAX, -FLT_MAX};
    int   ri[3] = {1 << 30, 1 << 30, 1 << 30};
#pragma unroll
    for (int k = 0; k < 4; ++k) {
        int i = tid + k * 256;
        insert3(g_winsum[b * 1024 + i], i, rv, ri);
    }

    // Warp-level merge of sorted triples.
#pragma unroll
    for (int o = 16; o > 0; o >>= 1) {
        float ov[3]; int oi[3];
#pragma unroll
        for (int s = 0; s < 3; ++s) {
            ov[s] = __shfl_down_sync(0xffffffffu, rv[s], o);
            oi[s] = __shfl_down_sync(0xffffffffu, ri[s], o);
        }
#pragma unroll
        for (int s = 0; s < 3; ++s) insert3(ov[s], oi[s], rv, ri);
    }
    if (lane == 0) {
#pragma unroll
        for (int s = 0; s < 3; ++s) { wv[warp][s] = rv[s]; wi[warp][s] = ri[s]; }
    }
    __syncthreads();

    // Warp 0 merges the 8 warp triples.
    if (warp == 0) {
        float fv[3] = {-FLT_MAX, -FLT_MAX, -FLT_MAX};
        int   fi[3] = {1 << 30, 1 << 30, 1 << 30};
        if (lane < 8) {
#pragma unroll
            for (int s = 0; s < 3; ++s) { fv[s] = wv[lane][s]; fi[s] = wi[lane][s]; }
        }
#pragma unroll
        for (int o = 4; o > 0; o >>= 1) {
            float ov[3]; int oi[3];
#pragma unroll
            for (int s = 0; s < 3; ++s) {
                ov[s] = __shfl_down_sync(0xffffffffu, fv[s], o);
                oi[s] = __shfl_down_sync(0xffffffffu, fi[s], o);
            }
#pragma unroll
            for (int s = 0; s < 3; ++s) insert3(ov[s], oi[s], fv, fi);
        }
        if (lane == 0) {
#pragma unroll
            for (int s = 0; s < 3; ++s) sidx[s] = fi[s];
        }
    }
    __syncthreads();

    const float wa[4] = {1.f, 0.75f, 0.25f, 0.f};
    const float wb[4] = {0.f, 0.25f, 0.75f, 1.f};
    int c = tid;

#pragma unroll
    for (int t = 0; t < 3; ++t) {
        int widx = sidx[t];
        int wh = widx >> 5, ww = widx & 31;
        const float* p = x + ((size_t)b * 4096 + wh * 128 + ww * 2) * 256 + c;
        float v00 = p[0];          // (i=0,j=0)
        float v01 = p[256];        // (i=0,j=1)
        float v10 = p[64 * 256];   // (i=1,j=0)
        float v11 = p[65 * 256];   // (i=1,j=1)

        float* ob = out + ((size_t)b * 48 + t * 16) * 256 + c;
#pragma unroll
        for (int gh = 0; gh < 4; ++gh) {
            float u0 = wa[gh] * v00 + wb[gh] * v10;  // interp along i (rows)
            float u1 = wa[gh] * v01 + wb[gh] * v11;
#pragma unroll
            for (int gw = 0; gw < 4; ++gw) {
                float val = wa[gw] * u0 + wb[gw] * u1;  // interp along j (cols)
                ob[(gh * 4 + gw) * 256] = val * s_gmap[gh * 4 + gw];
            }
        }
    }
}

// ---------------------------------------------------------------------------
extern "C" void kernel_launch(void* const* d_in, const int* in_sizes, int n_in,
                              void* d_out, int out_size) {
    const float* z   = (const float*)d_in[0];
    const float* x   = (const float*)d_in[1];
    const float* gth = (const float*)d_in[2];
    const float* gsg = (const float*)d_in[3];
    const float* glm = (const float*)d_in[4];
    const float* gps = (const float*)d_in[5];
    const float* ggm = (const float*)d_in[6];
    const float* gwt = (const float*)d_in[7];
    float* out = (float*)d_out;

    int B = in_sizes[0] / (64 * 256);   // z is (B, 64, 256)

    k_zmax  <<<B * 4 + 1, 256>>>(z, B, gth, gsg, glm, gps, ggm, gwt);
    k_winsum<<<B * 32,    256>>>(x);
    k_tail  <<<B,         256>>>(x, out);
}

// round 6
// speedup vs baseline: 1.0245x; 1.0063x over previous
#include <cuda_runtime.h>
#include <math_constants.h>
#include <float.h>

// Problem constants (fixed by setup_inputs): B=64, Nt=64, Ns=4096, C=256,
// WIN=2, TOPK=3, GH=GW=4, 16 gabor kernels.
#define BMAX 64

__device__ float g_winsum[BMAX * 1024];
__device__ float g_gmap[16];

__device__ __forceinline__ float4 max4(float4 a, float4 b) {
    return make_float4(fmaxf(a.x, b.x), fmaxf(a.y, b.y),
                       fmaxf(a.z, b.z), fmaxf(a.w, b.w));
}

// better(v,i, w,j): strictly greater value, or equal value with lower index
// (matches jax.lax.top_k ordering).
__device__ __forceinline__ bool better(float v, int i, float w, int j) {
    return v > w || (v == w && i < j);
}
__device__ __forceinline__ void insert3(float v, int i, float* rv, int* ri) {
    if (better(v, i, rv[0], ri[0])) {
        rv[2] = rv[1]; ri[2] = ri[1];
        rv[1] = rv[0]; ri[1] = ri[0];
        rv[0] = v;     ri[0] = i;
    } else if (better(v, i, rv[1], ri[1])) {
        rv[2] = rv[1]; ri[2] = ri[1];
        rv[1] = v;     ri[1] = i;
    } else if (better(v, i, rv[2], ri[2])) {
        rv[2] = v;     ri[2] = i;
    }
}

// ---------------------------------------------------------------------------
// Main kernel. grid = B*32 + 1.
// Block B*32: 4x4 gabor map, fully parallel (16 cells x 16 kernels).
// Blocks [0, B*32): b = blk>>5, wh = blk&31. Each block:
//   1. zmax[b] preamble: 256 threads = 4 token-groups x 64 float4 lanes,
//      16 loads each, smem max-reduce. Redundant across the 32 blocks of a
//      batch, but z is 4MB total so replays are L2 hits and overlap the
//      latency-bound start of the x stream.
//   2. winsum[b, wh*32+ww] = sum_{i,j} dot(x[b,(2wh+i)*64+2ww+j,:], zmax[b,:])
//      8 warps; warp owns 4 windows; 8 streaming (__ldcs) float4 loads
//      front-batched per row-pair; shuffle-reduce at the end.
// ---------------------------------------------------------------------------
__global__ void __launch_bounds__(256) k_main(
        const float* __restrict__ x, const float* __restrict__ z, int B,
        const float* __restrict__ gth, const float* __restrict__ gsg,
        const float* __restrict__ glm, const float* __restrict__ gps,
        const float* __restrict__ ggm, const float* __restrict__ gwt) {
    int blk = blockIdx.x;
    int tid = threadIdx.x;

    if (blk == B * 32) {   // gabor block
        int cell = tid >> 4;       // 0..15 -> (h,w)
        int k    = tid & 15;       // gabor kernel index
        int h = cell >> 2, w = cell & 3;
        float yy = (float)h - 1.5f;
        float xx = (float)w - 1.5f;
        float theta = gth[k] * (2.f * CUDART_PI_F);
        float ct = cosf(theta), st = sinf(theta);
        float xp =  xx * ct + yy * st;
        float yp = -xx * st + yy * ct;
        float sig = gsg[k] + 0.5f;
        float lmb = glm[k] + 0.5f;
        float gam = ggm[k];
        float env = expf(-(xp * xp + gam * gam * yp * yp) / (2.f * sig * sig));
        float car = cosf(2.f * CUDART_PI_F * xp / lmb + gps[k]);
        float term = gwt[k] * env * car;
#pragma unroll
        for (int o = 8; o > 0; o >>= 1)
            term += __shfl_down_sync(0xffffffffu, term, o, 16);
        if (k == 0) g_gmap[cell] = 1.f + term;  // splat + x_up = x_up*(1+gmap)
        return;
    }

    int b  = blk >> 5;
    int wh = blk & 31;
    __shared__ float4 szg[4][64];
    __shared__ float4 sz[64];

    // --- zmax[b] preamble ---
    {
        int g  = tid >> 6;       // token group 0..3 (16 tokens each)
        int c4 = tid & 63;       // float4 channel lane
        const float4* zp = (const float4*)(z + ((size_t)b * 64 + g * 16) * 256) + c4;
        float4 m = __ldg(zp);
#pragma unroll
        for (int t = 1; t < 16; ++t) m = max4(m, __ldg(zp + t * 64));
        szg[g][c4] = m;
    }
    __syncthreads();
    if (tid < 64)
        sz[tid] = max4(max4(szg[0][tid], szg[1][tid]),
                       max4(szg[2][tid], szg[3][tid]));
    __syncthreads();

    int warp = tid >> 5, lane = tid & 31;
    const float* xb = x + (size_t)b * 4096 * 256 + (size_t)wh * 128 * 256
                        + (size_t)warp * 4 * 2 * 256;

    float acc[4] = {0.f, 0.f, 0.f, 0.f};
#pragma unroll
    for (int r = 0; r < 4; ++r) {
        int off = ((r >> 1) * 64 + (r & 1)) * 256;   // rows s, s+1, s+64, s+65
        float4 va[4], vb[4];
#pragma unroll
        for (int q = 0; q < 4; ++q) {                // batch 8 loads before FMAs
            const float4* p4 = (const float4*)(xb + q * 512 + off);
            va[q] = __ldcs(p4 + lane);
            vb[q] = __ldcs(p4 + lane + 32);
        }
        float4 za = sz[lane], zb = sz[lane + 32];
#pragma unroll
        for (int q = 0; q < 4; ++q) {
            acc[q] += va[q].x * za.x + va[q].y * za.y + va[q].z * za.z + va[q].w * za.w;
            acc[q] += vb[q].x * zb.x + vb[q].y * zb.y + vb[q].z * zb.z + vb[q].w * zb.w;
        }
    }
#pragma unroll
    for (int q = 0; q < 4; ++q) {
        float a = acc[q];
#pragma unroll
        for (int o = 16; o > 0; o >>= 1) a += __shfl_down_sync(0xffffffffu, a, o);
        if (lane == 0) g_winsum[b * 1024 + wh * 32 + warp * 4 + q] = a;
    }
}

// ---------------------------------------------------------------------------
// Tail: per-batch top-3 via warp-shuffle triple merge (2 barriers total),
// then gather + bilinear 2->4 upsample + (1+gmap) scale + write.
// One block per batch, thread per channel.
// jax half-pixel bilinear 2->4 weights: {1,0},{.75,.25},{.25,.75},{0,1}.
// ---------------------------------------------------------------------------
__global__ void __launch_bounds__(256) k_tail(const float* __restrict__ x,
                                              float* __restrict__ out) {
    int b = blockIdx.x;
    __shared__ float wv[8][3];
    __shared__ int   wi[8][3];
    __shared__ int   sidx[3];
    __shared__ float s_gmap[16];
    int tid = threadIdx.x;
    int warp = tid >> 5, lane = tid & 31;

    if (tid < 16) s_gmap[tid] = g_gmap[tid];

    // Local top-3 over this thread's 4 values.
    float rv[3] = {-FLT_MAX, -FLT_MAX, -FLT_MAX};
    int   ri[3] = {1 << 30, 1 << 30, 1 << 30};
#pragma unroll
    for (int k = 0; k < 4; ++k) {
        int i = tid + k * 256;
        insert3(g_winsum[b * 1024 + i], i, rv, ri);
    }

    // Warp-level merge of sorted triples.
#pragma unroll
    for (int o = 16; o > 0; o >>= 1) {
        float ov[3]; int oi[3];
#pragma unroll
        for (int s = 0; s < 3; ++s) {
            ov[s] = __shfl_down_sync(0xffffffffu, rv[s], o);
            oi[s] = __shfl_down_sync(0xffffffffu, ri[s], o);
        }
#pragma unroll
        for (int s = 0; s < 3; ++s) insert3(ov[s], oi[s], rv, ri);
    }
    if (lane == 0) {
#pragma unroll
        for (int s = 0; s < 3; ++s) { wv[warp][s] = rv[s]; wi[warp][s] = ri[s]; }
    }
    __syncthreads();

    // Warp 0 merges the 8 warp triples.
    if (warp == 0) {
        float fv[3] = {-FLT_MAX, -FLT_MAX, -FLT_MAX};
        int   fi[3] = {1 << 30, 1 << 30, 1 << 30};
        if (lane < 8) {
#pragma unroll
            for (int s = 0; s < 3; ++s) { fv[s] = wv[lane][s]; fi[s] = wi[lane][s]; }
        }
#pragma unroll
        for (int o = 4; o > 0; o >>= 1) {
            float ov[3]; int oi[3];
#pragma unroll
            for (int s = 0; s < 3; ++s) {
                ov[s] = __shfl_down_sync(0xffffffffu, fv[s], o);
                oi[s] = __shfl_down_sync(0xffffffffu, fi[s], o);
            }
#pragma unroll
            for (int s = 0; s < 3; ++s) insert3(ov[s], oi[s], fv, fi);
        }
        if (lane == 0) {
#pragma unroll
            for (int s = 0; s < 3; ++s) sidx[s] = fi[s];
        }
    }
    __syncthreads();

    const float wa[4] = {1.f, 0.75f, 0.25f, 0.f};
    const float wb[4] = {0.f, 0.25f, 0.75f, 1.f};
    int c = tid;

#pragma unroll
    for (int t = 0; t < 3; ++t) {
        int widx = sidx[t];
        int wh = widx >> 5, ww = widx & 31;
        const float* p = x + ((size_t)b * 4096 + wh * 128 + ww * 2) * 256 + c;
        float v00 = p[0];          // (i=0,j=0)
        float v01 = p[256];        // (i=0,j=1)
        float v10 = p[64 * 256];   // (i=1,j=0)
        float v11 = p[65 * 256];   // (i=1,j=1)

        float* ob = out + ((size_t)b * 48 + t * 16) * 256 + c;
#pragma unroll
        for (int gh = 0; gh < 4; ++gh) {
            float u0 = wa[gh] * v00 + wb[gh] * v10;  // interp along i (rows)
            float u1 = wa[gh] * v01 + wb[gh] * v11;
#pragma unroll
            for (int gw = 0; gw < 4; ++gw) {
                float val = wa[gw] * u0 + wb[gw] * u1;  // interp along j (cols)
                ob[(gh * 4 + gw) * 256] = val * s_gmap[gh * 4 + gw];
            }
        }
    }
}

// ---------------------------------------------------------------------------
extern "C" void kernel_launch(void* const* d_in, const int* in_sizes, int n_in,
                              void* d_out, int out_size) {
    const float* z   = (const float*)d_in[0];
    const float* x   = (const float*)d_in[1];
    const float* gth = (const float*)d_in[2];
    const float* gsg = (const float*)d_in[3];
    const float* glm = (const float*)d_in[4];
    const float* gps = (const float*)d_in[5];
    const float* ggm = (const float*)d_in[6];
    const float* gwt = (const float*)d_in[7];
    float* out = (float*)d_out;

    int B = in_sizes[0] / (64 * 256);   // z is (B, 64, 256)

    k_main<<<B * 32 + 1, 256>>>(x, z, B, gth, gsg, glm, gps, ggm, gwt);
    k_tail<<<B,          256>>>(x, out);
}